// round 9
// baseline (speedup 1.0000x reference)
#include <cuda_runtime.h>

#define FULLMASK 0xFFFFFFFFu

// Persistent ticket-balanced EMA scan.
// One warp processes 4096-element SEGMENTS of (b,c) rows pulled from a global
// ticket counter (perfect load balance, no wave-quantization tail). Segments
// are independent via a decayed warm-up halo (g^halo < 1e-10 => exact at
// fp32; clamps to row start / exact full-scan fallback if g ~ 1).
// Tile = 256 elements (lane owns 8 contiguous = two float4s):
//   per-lane 8-elem chain tail -> warp Kogge-Stone over lane tails (ratio
//   g^8) -> cross-tile carry with g^256 -> outputs reconstructed with the
//   exact serial recurrence seeded from the scan state.
// Prefetch depth 1 (the R6 optimum: 48 regs, steady 2-load stream).

__device__ unsigned int g_ticket;

__global__ void ema_reset_ticket_kernel() { g_ticket = 0u; }

__global__ void __launch_bounds__(128, 10)
ema_persist_kernel(const float4* __restrict__ x4,
                   const float* __restrict__ w,
                   float4* __restrict__ out4,
                   int Cdim, int T, int nrows, int nseg)
{
    constexpr int SEG_TILES = 16;             // 16 * 256 = 4096 elems/segment
    const int lane  = threadIdx.x & 31;
    const int total = nrows * nseg;

    for (;;) {
        unsigned int s = 0;
        if (lane == 0) s = atomicAdd(&g_ticket, 1u);
        s = __shfl_sync(FULLMASK, s, 0);
        if (s >= (unsigned int)total) break;

        const int row = (int)s / nseg;
        const int seg = (int)s - row * nseg;

        const float g   = __ldg(&w[row % Cdim]);
        const float omg = 1.0f - g;

        const float g2   = g * g;
        const float g4   = g2 * g2;
        const float g8   = g4 * g4;           // lane-step ratio
        const float g16  = g8 * g8;
        const float g32  = g16 * g16;
        const float g64  = g32 * g32;
        const float g128 = g64 * g64;
        const float g256 = g128 * g128;       // tile-step ratio

        // g^(8*lane) by binary decomposition
        float pl = 1.0f;
        if (lane & 1)  pl *= g8;
        if (lane & 2)  pl *= g16;
        if (lane & 4)  pl *= g32;
        if (lane & 8)  pl *= g64;
        if (lane & 16) pl *= g128;

        // warm-up tiles: g^(256*wt) < 1e-10; exact fallback if g ~ 1
        int wt;
        if (g > 0.0f && g < 0.9999f)
            wt = (int)((-23.03f * (1.0f / 256.0f)) / __logf(g)) + 1;
        else
            wt = 0x3fffffff;
        const int seg_tile0 = seg * SEG_TILES;
        if (wt > seg_tile0) wt = seg_tile0;
        if (wt < 0) wt = 0;

        const float4* __restrict__ xin  = x4   + (size_t)row * (T >> 2);
        float4*       __restrict__ yout = out4 + (size_t)row * (T >> 2);

        const int tile_begin = seg_tile0 - wt;
        const int count      = wt + SEG_TILES;

        float C = 0.0f;

        int base = tile_begin * 64 + 2 * lane;
        float4 a0 = __ldcs(xin + base);
        float4 a1 = __ldcs(xin + base + 1);

        #pragma unroll 1
        for (int t = 0; t < count; ++t) {
            // prefetch next tile while this one is scanned
            float4 n0 = a0, n1 = a1;
            if (t + 1 < count) {
                n0 = __ldcs(xin + base + 64);
                n1 = __ldcs(xin + base + 65);
            }

            // per-lane chain tail over 8 contiguous elements
            float l = a0.x * omg;
            l = fmaf(g, l, a0.y * omg);
            l = fmaf(g, l, a0.z * omg);
            l = fmaf(g, l, a0.w * omg);
            l = fmaf(g, l, a1.x * omg);
            l = fmaf(g, l, a1.y * omg);
            l = fmaf(g, l, a1.z * omg);
            l = fmaf(g, l, a1.w * omg);

            // warp inclusive scan of lane tails, ratio g^8
            float v = l, tv;
            tv = __shfl_up_sync(FULLMASK, v, 1);  if (lane >= 1)  v = fmaf(g8,   tv, v);
            tv = __shfl_up_sync(FULLMASK, v, 2);  if (lane >= 2)  v = fmaf(g16,  tv, v);
            tv = __shfl_up_sync(FULLMASK, v, 4);  if (lane >= 4)  v = fmaf(g32,  tv, v);
            tv = __shfl_up_sync(FULLMASK, v, 8);  if (lane >= 8)  v = fmaf(g64,  tv, v);
            tv = __shfl_up_sync(FULLMASK, v, 16); if (lane >= 16) v = fmaf(g128, tv, v);

            // exclusive carry from earlier lanes
            float cL = __shfl_up_sync(FULLMASK, v, 1);
            if (lane == 0) cL = 0.0f;

            if (t >= wt) {
                // EMA state just before this lane's first element, then
                // exact serial reconstruction of the 8 outputs
                float y = fmaf(pl, C, cL);
                float4 o0, o1;
                y = fmaf(g, y, a0.x * omg);  o0.x = y;
                y = fmaf(g, y, a0.y * omg);  o0.y = y;
                y = fmaf(g, y, a0.z * omg);  o0.z = y;
                y = fmaf(g, y, a0.w * omg);  o0.w = y;
                y = fmaf(g, y, a1.x * omg);  o1.x = y;
                y = fmaf(g, y, a1.y * omg);  o1.y = y;
                y = fmaf(g, y, a1.z * omg);  o1.z = y;
                y = fmaf(g, y, a1.w * omg);  o1.w = y;
                __stcs(yout + base,     o0);
                __stcs(yout + base + 1, o1);
            }

            // cross-tile carry
            C = fmaf(g256, C, __shfl_sync(FULLMASK, v, 31));

            a0 = n0; a1 = n1;
            base += 64;
        }
    }
}

extern "C" void kernel_launch(void* const* d_in, const int* in_sizes, int n_in,
                              void* d_out, int out_size)
{
    const float4* x4 = (const float4*)d_in[0];
    const float*  w  = (const float*)d_in[1];
    float4* out4 = (float4*)d_out;

    const int Cdim  = in_sizes[1];          // 512
    const int T     = 16384;                // fixed problem shape
    const int nrows = in_sizes[0] / T;      // B*C = 4096
    const int nseg  = T / 4096;             // 4 segments per row

    // reset the ticket, then run a persistent grid (~10 blocks/SM on 152 SMs)
    ema_reset_ticket_kernel<<<1, 1>>>();
    dim3 block(128);
    dim3 grid(1520);
    ema_persist_kernel<<<grid, block>>>(x4, w, out4, Cdim, T, nrows, nseg);
}